// round 8
// baseline (speedup 1.0000x reference)
#include <cuda_runtime.h>
#include <cuda_bf16.h>
#include <cstdint>

// pred (N=8, V=3, C=24, T=8, H=128, W=128) fp32; mask (N,H,W) i32 {0,1};
// vq_0 (1,C) fp32. out = sum(|pred - vq0[c]| * (1-mask)) / (sum(1-mask)*V*C*T)
//
// R7: contiguity-first tiling. Work unit = half an (n,vct) plane = 32KB of
// pred read FULLY SEQUENTIALLY by the block (256 threads x 8 consecutive
// float4 sweeps) -> long DRAM bursts instead of 4KB hops at 64KB stride.
// vq is uniform per unit (smem broadcast). Mask re-read per unit from L2
// (mask fits L2: 512KB; extra ~75MB L2 traffic, zero extra DRAM).
// Persistent single-wave grid (148x8), dynamic tickets (9216 units),
// last block finalizes + resets globals for graph replay.

#define CTOT    24
#define HW4     4096              // 128*128/4
#define VCT     576
#define NPLANES 4608              // N * VCT
#define NUNITS  9216              // 2 half-planes per plane
#define JPER    8                 // float4 sweeps per unit (8*256 = 2048 = HW4/2)
#define NBLOCKS 1184              // 148 SMs * 8

__device__ double              g_num;
__device__ unsigned long long  g_cnt;
__device__ unsigned            g_work;
__device__ unsigned            g_ticket;

__global__ void __launch_bounds__(256, 8)
fused_kernel(const float4* __restrict__ pred,
             const int4*   __restrict__ mask,
             const float*  __restrict__ vq0,
             float*        __restrict__ out) {
    __shared__ float vqtab[VCT];
    for (int i = threadIdx.x; i < VCT; i += 256) {
        int c = (i >> 3) % CTOT;          // vct = (v*C + c)*T + t
        vqtab[i] = vq0[c];
    }

    __shared__ unsigned cur_unit;
    float acc = 0.f;
    unsigned long long cnt = 0ull;

    for (;;) {
        __syncthreads();                  // protect cur_unit reuse (covers vqtab init)
        if (threadIdx.x == 0)
            cur_unit = atomicAdd(&g_work, 1u);
        __syncthreads();
        unsigned u = cur_unit;
        if (u >= NUNITS) break;

        unsigned p    = u >> 1;           // plane id: n*VCT + vct
        unsigned half = u & 1u;
        unsigned n    = p / VCT;
        unsigned vct  = p - n * VCT;
        float v = vqtab[vct];             // uniform across block

        unsigned base = half * 2048u + threadIdx.x;
        const float4* pp = pred + (size_t)p * HW4;
        const int4*   mp = mask + (size_t)n * HW4;

        #pragma unroll
        for (int j = 0; j < JPER; j++) {
            unsigned idx = base + (unsigned)j * 256u;
            int4   m = __ldg(&mp[idx]);
            float4 q = __ldcs(&pp[idx]);  // streaming: evict-first
            float wx = (m.x == 0) ? 1.f : 0.f;
            float wy = (m.y == 0) ? 1.f : 0.f;
            float wz = (m.z == 0) ? 1.f : 0.f;
            float ww = (m.w == 0) ? 1.f : 0.f;
            cnt += (unsigned)((m.x == 0) + (m.y == 0) + (m.z == 0) + (m.w == 0));
            acc = fmaf(fabsf(q.x - v), wx, acc);
            acc = fmaf(fabsf(q.y - v), wy, acc);
            acc = fmaf(fabsf(q.z - v), wz, acc);
            acc = fmaf(fabsf(q.w - v), ww, acc);
        }
    }

    // block reduce
    #pragma unroll
    for (int off = 16; off; off >>= 1) {
        acc += __shfl_xor_sync(0xFFFFFFFFu, acc, off);
        cnt += __shfl_xor_sync(0xFFFFFFFFu, cnt, off);
    }
    __shared__ float              warp_sum[8];
    __shared__ unsigned long long warp_cnt[8];
    int lane = threadIdx.x & 31, wid = threadIdx.x >> 5;
    if (lane == 0) { warp_sum[wid] = acc; warp_cnt[wid] = cnt; }
    __syncthreads();

    __shared__ bool is_last;
    if (threadIdx.x == 0) {
        float s = 0.f;
        unsigned long long k = 0ull;
        #pragma unroll
        for (int w = 0; w < 8; w++) { s += warp_sum[w]; k += warp_cnt[w]; }
        atomicAdd(&g_num, (double)s);
        atomicAdd(&g_cnt, k);
        __threadfence();
        unsigned tk = atomicInc(&g_ticket, NBLOCKS - 1);
        is_last = (tk == NBLOCKS - 1);
    }
    __syncthreads();

    if (is_last && threadIdx.x == 0) {
        __threadfence();
        double num = *((volatile double*)&g_num);
        unsigned long long den = *((volatile unsigned long long*)&g_cnt);
        out[0] = (float)(num / (double)den);
        // reset for next graph replay (g_ticket already wrapped to 0)
        g_num  = 0.0;
        g_cnt  = 0ull;
        g_work = 0u;
        __threadfence();
    }
}

extern "C" void kernel_launch(void* const* d_in, const int* in_sizes, int n_in,
                              void* d_out, int out_size) {
    const float4* pred = (const float4*)d_in[0];
    const int4*   mask = (const int4*)d_in[1];
    const float*  vq0  = (const float*)d_in[2];
    float* out = (float*)d_out;

    fused_kernel<<<NBLOCKS, 256>>>(pred, mask, vq0, out);
}

// round 9
// speedup vs baseline: 1.0412x; 1.0412x over previous
#include <cuda_runtime.h>
#include <cuda_bf16.h>
#include <cstdint>

// pred (N=8, V=3, C=24, T=8, H=128, W=128) fp32; mask (N,H,W) i32 {0,1};
// vq_0 (1,C) fp32. out = sum(|pred - vq0[c]| * (1-mask)) / (sum(1-mask)*V*C*T)
//
// R6 winner structure (49.54us) with finer tiles (JPER=4, 18432 tiles) to
// smooth the end-of-kernel drain: 15.6 tiles/block halves the ragged-finish
// granularity; ticket/barrier overhead stays hidden by 8 blocks/SM.
// pred: __ldcs streaming; mask: __ldg, one int4 reused across 4 slices.
// Persistent single-wave grid, dynamic tickets, last block finalizes and
// resets globals for graph-replay determinism.

#define CTOT    24
#define HW4     4096              // 128*128/4
#define NPLANE4 2359296           // V*C*T*HW/4
#define VCT     576
#define JPER    4
#define NTILES  18432             // 144 chunks * 8 n * 4096 hw4 / 256 threads
#define NBLOCKS 1184              // 148 SMs * 8

__device__ double              g_num;
__device__ unsigned long long  g_cnt;
__device__ unsigned            g_work;
__device__ unsigned            g_ticket;

__global__ void __launch_bounds__(256, 8)
fused_kernel(const float4* __restrict__ pred,
             const int4*   __restrict__ mask,
             const float*  __restrict__ vq0,
             float*        __restrict__ out) {
    __shared__ float vqtab[VCT];
    for (int i = threadIdx.x; i < VCT; i += 256) {
        int c = (i >> 3) % CTOT;          // vct = (v*C + c)*T + t
        vqtab[i] = vq0[c];
    }

    __shared__ unsigned cur_tile;
    float acc = 0.f;
    unsigned long long cnt = 0ull;

    for (;;) {
        __syncthreads();                  // protect cur_tile reuse (covers vqtab init)
        if (threadIdx.x == 0)
            cur_tile = atomicAdd(&g_work, 1u);
        __syncthreads();
        unsigned t = cur_tile;
        if (t >= NTILES) break;

        unsigned tid   = t * 256u + threadIdx.x;
        unsigned hw4   = tid & (HW4 - 1);
        unsigned n     = (tid >> 12) & 7u;
        unsigned chunk = tid >> 15;       // 0..143
        unsigned nhw   = tid & 32767u;

        int4 m = __ldg(&mask[nhw]);
        float wx = (m.x == 0) ? 1.f : 0.f;
        float wy = (m.y == 0) ? 1.f : 0.f;
        float wz = (m.z == 0) ? 1.f : 0.f;
        float ww = (m.w == 0) ? 1.f : 0.f;
        cnt += (unsigned long long)((m.x == 0) + (m.y == 0) + (m.z == 0) + (m.w == 0)) * JPER;

        const float4* p  = pred + (size_t)n * NPLANE4 + (size_t)(chunk * JPER) * HW4 + hw4;
        const float*  vt = vqtab + chunk * JPER;

        #pragma unroll
        for (int j = 0; j < JPER; j++) {
            float4 q = __ldcs(&p[(size_t)j * HW4]);   // streaming: evict-first
            float v = vt[j];
            acc = fmaf(fabsf(q.x - v), wx, acc);
            acc = fmaf(fabsf(q.y - v), wy, acc);
            acc = fmaf(fabsf(q.z - v), wz, acc);
            acc = fmaf(fabsf(q.w - v), ww, acc);
        }
    }

    // block reduce
    #pragma unroll
    for (int off = 16; off; off >>= 1) {
        acc += __shfl_xor_sync(0xFFFFFFFFu, acc, off);
        cnt += __shfl_xor_sync(0xFFFFFFFFu, cnt, off);
    }
    __shared__ float              warp_sum[8];
    __shared__ unsigned long long warp_cnt[8];
    int lane = threadIdx.x & 31, wid = threadIdx.x >> 5;
    if (lane == 0) { warp_sum[wid] = acc; warp_cnt[wid] = cnt; }
    __syncthreads();

    __shared__ bool is_last;
    if (threadIdx.x == 0) {
        float s = 0.f;
        unsigned long long k = 0ull;
        #pragma unroll
        for (int w = 0; w < 8; w++) { s += warp_sum[w]; k += warp_cnt[w]; }
        atomicAdd(&g_num, (double)s);
        atomicAdd(&g_cnt, k);
        __threadfence();
        unsigned tk = atomicInc(&g_ticket, NBLOCKS - 1);
        is_last = (tk == NBLOCKS - 1);
    }
    __syncthreads();

    if (is_last && threadIdx.x == 0) {
        __threadfence();
        double num = *((volatile double*)&g_num);
        unsigned long long den = *((volatile unsigned long long*)&g_cnt);
        out[0] = (float)(num / (double)den);
        // reset for next graph replay (g_ticket already wrapped to 0)
        g_num  = 0.0;
        g_cnt  = 0ull;
        g_work = 0u;
        __threadfence();
    }
}

extern "C" void kernel_launch(void* const* d_in, const int* in_sizes, int n_in,
                              void* d_out, int out_size) {
    const float4* pred = (const float4*)d_in[0];
    const int4*   mask = (const int4*)d_in[1];
    const float*  vq0  = (const float*)d_in[2];
    float* out = (float*)d_out;

    fused_kernel<<<NBLOCKS, 256>>>(pred, mask, vq0, out);
}